// round 3
// baseline (speedup 1.0000x reference)
#include <cuda_runtime.h>
#include <math.h>

#define NB_C   100000
#define SZ_D   64
#define SZ_B   1024
#define BM     128
#define BN     128
#define KC     32          // k-chunk (2 chunks of 32 cover D=64)
#define CB     ((NB_C + BN - 1) / BN)   // 782 class blocks

// ---- device scratch (no allocations allowed) ----
__device__ float g_Pn[(size_t)NB_C * SZ_D];   // normalized proxies, 25.6 MB
__device__ float g_psq[NB_C];                 // sum(Pn^2) per class
__device__ float g_partial[(size_t)SZ_B * CB];// per (row, class-block) exp-sums
__device__ float g_persample[SZ_B];
__device__ int   g_ys[SZ_B];                  // decoded labels (dtype-robust)

// ============ Kernel 0: decode labels (int32 vs int64 robust) ============
// Reads only the first 1024 int32 words (4 KB) for detection — in-bounds for
// either dtype. int64 little-endian labels < 2^31 have all odd words == 0.
__global__ void decode_ys_kernel(const int* __restrict__ ys32) {
    __shared__ int nonzero_odd;
    const int tid = threadIdx.x;           // 1024 threads
    if (tid == 0) nonzero_odd = 0;
    __syncthreads();
    if (tid < SZ_B / 2) {
        if (ys32[2 * tid + 1] != 0) atomicOr(&nonzero_odd, 1);
    }
    __syncthreads();
    if (nonzero_odd) {
        g_ys[tid] = ys32[tid];                         // genuine int32 labels
    } else {
        const long long* ys64 = (const long long*)ys32; // int64 labels
        g_ys[tid] = (int)ys64[tid];
    }
}

// ================= Kernel A: row-normalize proxies =================
__global__ void normalize_kernel(const float* __restrict__ proxies) {
    int row  = blockIdx.x * 8 + (threadIdx.x >> 5);
    int lane = threadIdx.x & 31;
    if (row >= NB_C) return;
    const float2 v = *(const float2*)(proxies + (size_t)row * SZ_D + lane * 2);
    float s = v.x * v.x + v.y * v.y;
    #pragma unroll
    for (int o = 16; o; o >>= 1) s += __shfl_xor_sync(0xffffffffu, s, o);
    float norm = sqrtf(s);
    float inv  = 1.0f / fmaxf(norm, 1e-12f);
    float2 w; w.x = v.x * inv; w.y = v.y * inv;
    *(float2*)(g_Pn + (size_t)row * SZ_D + lane * 2) = w;
    if (lane == 0) g_psq[row] = s * inv * inv;
}

// ===== Kernel B: tiled GEMM + fused exp-sum epilogue (per class-block partials) =====
__global__ void __launch_bounds__(256, 2)
gemm_lse_kernel(const float* __restrict__ xs) {
    __shared__ float As[KC * BM];   // k-major: As[k*BM + r]
    __shared__ float Bs[KC * BN];   // k-major: Bs[k*BN + c]
    __shared__ float Qs[BN];        // psq tile
    __shared__ int   Ys[BM];        // labels for this row tile

    const int cb   = blockIdx.x;
    const int rb   = blockIdx.y;
    const int col0 = cb * BN;
    const int row0 = rb * BM;
    const int tid  = threadIdx.x;          // 256 threads
    const int tx   = tid & 15;             // class group
    const int ty   = tid >> 4;             // row group

    if (tid < BM) Ys[tid] = g_ys[row0 + tid];
    if (tid < BN) {
        int cls = col0 + tid;
        Qs[tid] = (cls < NB_C) ? g_psq[cls] : 0.0f;
    }

    float acc[8][8];
    #pragma unroll
    for (int i = 0; i < 8; i++)
        #pragma unroll
        for (int j = 0; j < 8; j++) acc[i][j] = 0.0f;

    #pragma unroll
    for (int kc = 0; kc < SZ_D / KC; kc++) {
        // -- load A tile (xs): 128 rows x 32 k --
        #pragma unroll
        for (int i = 0; i < 4; i++) {
            int idx = tid + i * 256;           // 0..1023
            int r   = idx & 127;
            int kq  = idx >> 7;                // 0..7 (float4 group)
            float4 v = *(const float4*)(xs + (size_t)(row0 + r) * SZ_D + kc * KC + kq * 4);
            int sb = (kq * 4) * BM + r;
            As[sb          ] = v.x;
            As[sb + BM     ] = v.y;
            As[sb + 2 * BM ] = v.z;
            As[sb + 3 * BM ] = v.w;
        }
        // -- load B tile (normalized proxies): 128 classes x 32 k (guard tail) --
        #pragma unroll
        for (int i = 0; i < 4; i++) {
            int idx = tid + i * 256;
            int c   = idx & 127;
            int kq  = idx >> 7;
            int cls = col0 + c;
            float4 v = make_float4(0.f, 0.f, 0.f, 0.f);
            if (cls < NB_C)
                v = *(const float4*)(g_Pn + (size_t)cls * SZ_D + kc * KC + kq * 4);
            int sb = (kq * 4) * BN + c;
            Bs[sb          ] = v.x;
            Bs[sb + BN     ] = v.y;
            Bs[sb + 2 * BN ] = v.z;
            Bs[sb + 3 * BN ] = v.w;
        }
        __syncthreads();

        #pragma unroll 8
        for (int k = 0; k < KC; k++) {
            float av[8], bv[8];
            *(float4*)&av[0] = *(const float4*)(As + k * BM + ty * 8);
            *(float4*)&av[4] = *(const float4*)(As + k * BM + ty * 8 + 4);
            *(float4*)&bv[0] = *(const float4*)(Bs + k * BN + tx * 8);
            *(float4*)&bv[4] = *(const float4*)(Bs + k * BN + tx * 8 + 4);
            #pragma unroll
            for (int i = 0; i < 8; i++)
                #pragma unroll
                for (int j = 0; j < 8; j++)
                    acc[i][j] = fmaf(av[i], bv[j], acc[i][j]);
        }
        __syncthreads();
    }

    // -- epilogue: g = 2*dot - psq ; sum exp(g) over valid negatives --
    int yv[8];
    float qs[8];
    #pragma unroll
    for (int i = 0; i < 8; i++) yv[i] = Ys[ty * 8 + i];
    #pragma unroll
    for (int j = 0; j < 8; j++) qs[j] = Qs[tx * 8 + j];

    const int cls_base = col0 + tx * 8;
    float rowsum[8];
    #pragma unroll
    for (int i = 0; i < 8; i++) {
        float s = 0.0f;
        #pragma unroll
        for (int j = 0; j < 8; j++) {
            int cls = cls_base + j;
            float g = fmaf(2.0f, acc[i][j], -qs[j]);
            float e = __expf(g);
            if (cls >= NB_C || cls == yv[i]) e = 0.0f;
            s += e;
        }
        rowsum[i] = s;
    }
    // reduce across the 16 tx lanes (xor 8..1 stays within each 16-lane half-warp)
    #pragma unroll
    for (int i = 0; i < 8; i++) {
        float s = rowsum[i];
        #pragma unroll
        for (int o = 8; o >= 1; o >>= 1) s += __shfl_xor_sync(0xffffffffu, s, o);
        rowsum[i] = s;
    }
    if (tx == 0) {
        #pragma unroll
        for (int i = 0; i < 8; i++) {
            int row = row0 + ty * 8 + i;
            g_partial[(size_t)row * CB + cb] = rowsum[i];
        }
    }
}

// ===== Kernel C: per-row combine partials + positive distance =====
__global__ void combine_kernel(const float* __restrict__ xs) {
    const int row = blockIdx.x;
    const int tid = threadIdx.x;   // 128 threads
    const int y   = g_ys[row];

    float S = 0.0f;
    for (int p = tid; p < CB; p += 128) S += g_partial[(size_t)row * CB + p];

    float d = 0.0f;
    if (tid < SZ_D) d = xs[(size_t)row * SZ_D + tid] * g_Pn[(size_t)y * SZ_D + tid];

    #pragma unroll
    for (int o = 16; o; o >>= 1) {
        S += __shfl_xor_sync(0xffffffffu, S, o);
        d += __shfl_xor_sync(0xffffffffu, d, o);
    }
    __shared__ float sS[4], sD[4];
    int w = tid >> 5, lane = tid & 31;
    if (lane == 0) { sS[w] = S; sD[w] = d; }
    __syncthreads();
    if (tid == 0) {
        float St = sS[0] + sS[1] + sS[2] + sS[3];
        float Dt = sD[0] + sD[1] + sD[2] + sD[3];
        // per_sample = d_pos + log_n ; the ||x||^2 terms cancel exactly
        g_persample[row] = g_psq[y] - 2.0f * Dt + logf(St);
    }
}

// ===== Kernel D: mean over batch =====
__global__ void mean_kernel(float* __restrict__ out) {
    const int tid = threadIdx.x;   // 1024
    float v = g_persample[tid];
    #pragma unroll
    for (int o = 16; o; o >>= 1) v += __shfl_xor_sync(0xffffffffu, v, o);
    __shared__ float s[32];
    int w = tid >> 5, lane = tid & 31;
    if (lane == 0) s[w] = v;
    __syncthreads();
    if (tid < 32) {
        float t = s[tid];
        #pragma unroll
        for (int o = 16; o; o >>= 1) t += __shfl_xor_sync(0xffffffffu, t, o);
        if (tid == 0) out[0] = t * (1.0f / (float)SZ_B);
    }
}

extern "C" void kernel_launch(void* const* d_in, const int* in_sizes, int n_in,
                              void* d_out, int out_size) {
    const float* xs      = (const float*)d_in[0];
    const int*   ys_raw  = (const int*)d_in[1];
    const float* proxies = (const float*)d_in[2];
    float*       out     = (float*)d_out;

    decode_ys_kernel<<<1, SZ_B>>>(ys_raw);
    normalize_kernel<<<(NB_C + 7) / 8, 256>>>(proxies);
    gemm_lse_kernel<<<dim3(CB, SZ_B / BM), 256>>>(xs);
    combine_kernel<<<SZ_B, 128>>>(xs);
    mean_kernel<<<1, SZ_B>>>(out);
}